// round 8
// baseline (speedup 1.0000x reference)
#include <cuda_runtime.h>
#include <cstdint>

// CTC forward, LOG2 domain, pure f32.
// One CTA per batch element; 416 threads; each thread owns a PAIR of states
// (even=blank, odd=label) stored as float2 in smem (double-buffered).
// logaddexp computed with the max-term-eliminated form (max contributes
// exactly 1): even = 1 ex2 + 1 lg2, odd = 2 ex2 + 1 lg2.
// Per-thread depth-4 register prefetch queues for blank + label log-probs.
// One barrier per step. Batch mean folded in via last-CTA atomic.

#define T_DIM 2000
#define V_DIM 256
#define S_DIM 400
#define L_DIM 801
#define NT    416           // 13 warps; threads 0..400 hold states, rest idle
#define NPAIR 417           // guard pair [0] + 416 data pairs
#define NEGF  (-1e30f)

__device__ float g_partial[64];
__device__ int   g_ctr = 0;

__device__ __forceinline__ float ex2f(float x) {
    float y; asm("ex2.approx.f32 %0, %1;" : "=f"(y) : "f"(x)); return y;
}
__device__ __forceinline__ float lg2f(float x) {
    float y; asm("lg2.approx.f32 %0, %1;" : "=f"(y) : "f"(x)); return y;
}

__global__ __launch_bounds__(NT, 1)
void ctc_kernel(const float* __restrict__ logp,
                const int*   __restrict__ targets,
                const int*   __restrict__ ilen,
                const int*   __restrict__ tlen,
                float*       __restrict__ out,
                int B)
{
    __shared__ float2 abuf[2][NPAIR];   // [parity][pair]; pair 0 = guard (NEG)

    const int b   = blockIdx.x;
    const int tid = threadIdx.x;
    const float* lpb = logp + (size_t)b * T_DIM * V_DIM;
    const int il  = ilen[b];
    const int tl  = tlen[b];
    const int end = 2 * tl;
    const float l2e = 1.4426950408889634f;

    // thread owns states se = 2*tid (blank) and so = 2*tid+1 (label)
    const int se = 2 * tid, so = se + 1;
    int  lbl  = 1;
    bool skip = false;
    if (so < L_DIM) {                       // tid <= 399
        lbl = targets[b * S_DIM + tid];
        if (tid >= 1) skip = (lbl != targets[b * S_DIM + tid - 1]);
    }
    const bool ve = (se < L_DIM) && (se <= end);
    const bool vo = (so < L_DIM) && (so <= end);
    const float* gbp = lpb + 1;             // blank column
    const float* glp = lpb + lbl;           // own-label column
    const int lim = il - 1;

    // fill both buffers (incl. guards) with NEG
    for (int i = tid; i < 2 * NPAIR; i += NT)
        ((float2*)abuf)[i] = make_float2(NEGF, NEGF);
    __syncthreads();

    // ---- t = 0 init (states 0,1 live in thread 0) ----
    if (tid == 0)
        abuf[0][1] = make_float2(lpb[1] * l2e, lpb[lbl] * l2e);

    // prefetch queues, rows 1..4 (clamped; il >= 1000 so clamps are moot)
    float qb0 = gbp[(size_t)min(1, lim) * V_DIM];
    float qb1 = gbp[(size_t)min(2, lim) * V_DIM];
    float qb2 = gbp[(size_t)min(3, lim) * V_DIM];
    float qb3 = gbp[(size_t)min(4, lim) * V_DIM];
    float ql0 = glp[(size_t)min(1, lim) * V_DIM];
    float ql1 = glp[(size_t)min(2, lim) * V_DIM];
    float ql2 = glp[(size_t)min(3, lim) * V_DIM];
    float ql3 = glp[(size_t)min(4, lim) * V_DIM];
    __syncthreads();

    // ---- main recursion, one barrier per step ----
    #pragma unroll 4
    for (int t = 1; t < il; ++t) {
        const float2* prv = abuf[(t + 1) & 1];
        float2*       cur = abuf[t & 1];

        float2 own   = prv[tid + 1];   // prev[2i], prev[2i+1]
        float2 below = prv[tid];       // prev[2i-2], prev[2i-1]

        // even state: logaddexp2(prev[2i], prev[2i-1]) + lp_blank
        float xe = own.x, ye = below.y;
        float me = fmaxf(xe, ye);
        float s_e = 1.0f + ex2f(-fabsf(xe - ye));
        float nve = me + lg2f(s_e) + qb0 * l2e;

        // odd state: logaddexp2_3(prev[2i+1], prev[2i], skip?prev[2i-1]) + lp
        float x = own.y, y = own.x;
        float z = skip ? below.y : NEGF;
        float mo = fmaxf(fmaxf(x, y), z);
        bool  xm = (x >= y) && (x >= z);
        bool  zm = (!xm) && (z > y);
        float u  = xm ? y : x;
        float v  = zm ? y : z;
        float s_o = 1.0f + ex2f(u - mo) + ex2f(v - mo);
        float nvo = mo + lg2f(s_o) + ql0 * l2e;

        nve = ve ? nve : NEGF;
        nvo = vo ? nvo : NEGF;
        cur[tid + 1] = make_float2(nve, nvo);

        // rotate queues; fetch row t+4 (clamped) — renamed away by unroll
        qb0 = qb1; qb1 = qb2; qb2 = qb3;
        ql0 = ql1; ql1 = ql2; ql2 = ql3;
        {
            int rr = t + 4; rr = rr < lim ? rr : lim;
            qb3 = gbp[(size_t)rr * V_DIM];
            ql3 = glp[(size_t)rr * V_DIM];
        }
        __syncthreads();
    }

    // ---- epilogue: logaddexp2(fin[end], fin[end-1]) ----
    if (tid == 0) {
        const float* f = (const float*)&abuf[(il - 1) & 1][0]; // state s at f[2+s]
        float x = f[2 + end], y = f[1 + end];
        float m = fmaxf(x, y);
        float ll2 = m + lg2f(ex2f(x - m) + ex2f(y - m));
        float loss = -0.6931471805599453f * ll2;
        if (!(loss < 1e29f)) loss = 0.0f;
        g_partial[b] = loss / (float)tl;
        __threadfence();
        int done = atomicAdd(&g_ctr, 1);
        if (done == B - 1) {
            float v = 0.0f;
            for (int i = 0; i < B; ++i) v += g_partial[i];
            out[0] = v / (float)B;
            g_ctr = 0;                  // deterministic across graph replays
        }
    }
}

extern "C" void kernel_launch(void* const* d_in, const int* in_sizes, int n_in,
                              void* d_out, int out_size)
{
    const float* logp    = (const float*)d_in[0];
    const int*   targets = (const int*)d_in[1];
    const int*   il      = (const int*)d_in[2];
    const int*   tl      = (const int*)d_in[3];
    const int B = in_sizes[2];

    ctc_kernel<<<B, NT>>>(logp, targets, il, tl, (float*)d_out, B);
}

// round 9
// speedup vs baseline: 1.0182x; 1.0182x over previous
#include <cuda_runtime.h>
#include <cstdint>

// CTC forward, LOG2 domain, pure f32, PARITY-SPLIT layout.
// E[k] = state 2k (blank-emitting, 401 entries), O[k] = state 2k+1 (label,
// 400 entries). Warps 0-12 compute E (2-term logaddexp: 1 ex2 + 1 lg2),
// warps 13-25 compute O (3-term: 3 ex2 + 1 lg2). Warp-aligned role split,
// zero intra-warp divergence. One barrier per step. Per-thread register
// prefetch queue on its own logp column. Batch mean via last-CTA atomic.

#define T_DIM 2000
#define V_DIM 256
#define S_DIM 400
#define L_DIM 801
#define NT    832          // 26 warps
#define EOFF  416          // odd group starts here (warp 13)
#define NEGF  (-1e30f)

__device__ float g_partial[64];
__device__ int   g_ctr = 0;

__device__ __forceinline__ float ex2f(float x) {
    float y; asm("ex2.approx.f32 %0, %1;" : "=f"(y) : "f"(x)); return y;
}
__device__ __forceinline__ float lg2f(float x) {
    float y; asm("lg2.approx.f32 %0, %1;" : "=f"(y) : "f"(x)); return y;
}

__global__ __launch_bounds__(NT, 1)
void ctc_kernel(const float* __restrict__ logp,
                const int*   __restrict__ targets,
                const int*   __restrict__ ilen,
                const int*   __restrict__ tlen,
                float*       __restrict__ out,
                int B)
{
    __shared__ float Ebuf[2][402];   // [parity][k+1]; [*][0] = guard NEG
    __shared__ float Obuf[2][401];   // [parity][k+1]; [*][0] = guard NEG

    const int b   = blockIdx.x;
    const int tid = threadIdx.x;
    const float* lpb = logp + (size_t)b * T_DIM * V_DIM;
    const int il  = ilen[b];
    const int tl  = tlen[b];
    const float l2e = 1.4426950408889634f;
    const int lim = il - 1;

    const bool isEven  = tid < EOFF;
    const int  k       = isEven ? tid : tid - EOFF;
    const bool inrange = isEven ? (k <= 400) : (k <= 399);

    // own logp column + skip flag (odd only)
    int  col  = 1;                    // blank
    bool skip = false;
    if (!isEven && inrange) {
        col = targets[b * S_DIM + k];
        if (k >= 1) skip = (col != targets[b * S_DIM + k - 1]);
    }
    // validity: even state 2k needs 2k <= 2tl; odd 2k+1 <= 2tl -> k <= tl-1
    const bool valid = inrange && (isEven ? (k <= tl) : (k <= tl - 1));
    const float* gcol = lpb + col;

    // fill both parities of both buffers with NEG
    for (int i = tid; i < 2 * 402; i += NT) ((float*)Ebuf)[i] = NEGF;
    for (int i = tid; i < 2 * 401; i += NT) ((float*)Obuf)[i] = NEGF;
    __syncthreads();

    // ---- t = 0 init ----
    if (tid == 0)    Ebuf[0][1] = lpb[1]   * l2e;       // state 0
    if (tid == EOFF) Obuf[0][1] = lpb[col] * l2e;       // state 1

    // prefetch queue rows 1..4 (clamped)
    float q0 = gcol[(size_t)min(1, lim) * V_DIM];
    float q1 = gcol[(size_t)min(2, lim) * V_DIM];
    float q2 = gcol[(size_t)min(3, lim) * V_DIM];
    float q3 = gcol[(size_t)min(4, lim) * V_DIM];
    __syncthreads();

    // ---- main recursion, one barrier per step ----
    #pragma unroll 4
    for (int t = 1; t < il; ++t) {
        const float* Ep = Ebuf[(t + 1) & 1];
        const float* Op = Obuf[(t + 1) & 1];

        if (isEven) {
            // E'[k] = logaddexp2(E[k], O[k-1]) + q
            float x = Ep[k + 1], y = Op[k];
            float m = fmaxf(x, y);
            float s = 1.0f + ex2f(-fabsf(x - y));
            float nv = fmaf(q0, l2e, m + lg2f(s));
            nv = valid ? nv : NEGF;
            if (inrange) Ebuf[t & 1][k + 1] = nv;
        } else {
            // O'[k] = logaddexp2(O[k], E[k], skip? O[k-1]) + q
            float x = Op[k + 1], y = Ep[k + 1];
            float z = skip ? Op[k] : NEGF;
            float m = fmaxf(fmaxf(x, y), z);
            float s = ex2f(x - m) + ex2f(y - m) + ex2f(z - m);
            float nv = fmaf(q0, l2e, m + lg2f(s));
            nv = valid ? nv : NEGF;
            if (inrange) Obuf[t & 1][k + 1] = nv;
        }

        // rotate queue, fetch row t+4 (clamped; renamed away by unroll)
        q0 = q1; q1 = q2; q2 = q3;
        {
            int rr = t + 4; rr = rr < lim ? rr : lim;
            q3 = gcol[(size_t)rr * V_DIM];
        }
        __syncthreads();
    }

    // ---- epilogue: logaddexp2(E[tl], O[tl-1]) at final parity ----
    if (tid == 0) {
        int f = (il - 1) & 1;
        float x = Ebuf[f][tl + 1];     // state 2*tl
        float y = Obuf[f][tl];         // state 2*tl-1
        float m = fmaxf(x, y);
        float ll2 = m + lg2f(ex2f(x - m) + ex2f(y - m));
        float loss = -0.6931471805599453f * ll2;
        if (!(loss < 1e29f)) loss = 0.0f;
        g_partial[b] = loss / (float)tl;
        __threadfence();
        int done = atomicAdd(&g_ctr, 1);
        if (done == B - 1) {            // last CTA: final mean + reset
            float v = 0.0f;
            for (int i = 0; i < B; ++i) v += g_partial[i];
            out[0] = v / (float)B;
            g_ctr = 0;                  // deterministic across graph replays
        }
    }
}

extern "C" void kernel_launch(void* const* d_in, const int* in_sizes, int n_in,
                              void* d_out, int out_size)
{
    const float* logp    = (const float*)d_in[0];
    const int*   targets = (const int*)d_in[1];
    const int*   il      = (const int*)d_in[2];
    const int*   tl      = (const int*)d_in[3];
    const int B = in_sizes[2];

    ctc_kernel<<<B, NT>>>(logp, targets, il, tl, (float*)d_out, B);
}